// round 5
// baseline (speedup 1.0000x reference)
#include <cuda_runtime.h>

#define BB 16
#define NN 2048
#define EE 256
#define KCH 8

typedef unsigned long long ull;

// Scratch (__device__ globals; allocation-free rule)
__device__ float g_part[KCH][4][EE];     // partial folded coefficients
__device__ float g_minpart[4][BB * NN];  // per-quarter partial min scores (512KB)

// ---- f32x2 helpers ---------------------------------------------------------
__device__ __forceinline__ ull fma2(ull a, ull b, ull c) {
    ull d;
    asm("fma.rn.f32x2 %0, %1, %2, %3;" : "=l"(d) : "l"(a), "l"(b), "l"(c));
    return d;
}
union F2U { ull u; float2 f; };
__device__ __forceinline__ ull pack2(float lo, float hi) {
    F2U t; t.f = make_float2(lo, hi); return t.u;
}
__device__ __forceinline__ void mina(float2& m, ull v) {
    F2U t; t.u = v;
    m.x = fminf(m.x, t.f.x);
    m.y = fminf(m.y, t.f.y);
}

// ---------------------------------------------------------------------------
// Kernel 1 (fused): grid = 128 + KCH blocks, 256 threads.
//   blocks [0,128):  (tile, quarter) min blocks. Single-barrier deterministic
//                    compaction of the batch's probes into shared pair-SoA,
//                    then packed-f32x2 min over this block's probe quarter
//                    for 1024 nodes (G=4 register blocking).
//   blocks [128,..): K-split partial folded coefficients.
// ---------------------------------------------------------------------------
__global__ __launch_bounds__(256) void main1_kernel(
    const float*    __restrict__ locs,
    const unsigned* __restrict__ probe_raw,
    const float*    __restrict__ W_node,
    const float*    __restrict__ b_node,
    const float*    __restrict__ W_dist,
    const float*    __restrict__ b_dist,
    const float*    __restrict__ W_out)
{
    int blk = blockIdx.x;
    int tid = threadIdx.x;

    if (blk >= 128) {
        // ---- folded coefficients, K-chunk c ----
        int c = blk - 128;
        int e = tid;
        float a0 = 0.f, a1 = 0.f, cc = 0.f, dd = 0.f;
        int k0 = c * (EE / KCH);
        #pragma unroll 8
        for (int kk = 0; kk < EE / KCH; kk++) {
            int k = k0 + kk;
            float wt = W_out[k * EE + e];
            float wb = W_out[(EE + k) * EE + e];
            a0 = fmaf(W_node[k],      wt, a0);
            a1 = fmaf(W_node[EE + k], wt, a1);
            cc = fmaf(W_dist[k],      wb, cc);
            dd = fmaf(b_node[k], wt, dd);
            dd = fmaf(b_dist[k], wb, dd);
        }
        g_part[c][0][e] = a0;
        g_part[c][1][e] = a1;
        g_part[c][2][e] = cc;
        g_part[c][3][e] = dd;
        return;
    }

    // ---- min block: (tile, quarter) ----
    int tile  = blk >> 2;               // 0..31 (1024-node tiles)
    int s     = blk & 3;                // probe quarter
    int b     = tile >> 1;              // batch
    int nbase = (tile & 1) << 10;

    __shared__ float4 s_xy4[NN / 2];    // pair-SoA (x0,x1,y0,y1), 16KB
    __shared__ ull    s_zz [NN / 2];    // pair (z0,z1), 8KB
    __shared__ int    s_wc[64];         // counts, index = wid*8 + j

    // dtype detect on 512 words (valid reads under both candidate layouts)
    bool bad = false;
    #pragma unroll
    for (int j = 0; j < 2; j++) {
        unsigned v = probe_raw[b * 512 + j * 256 + tid];
        if (v != 0u && v != 1u && v != 0x3F800000u) bad = true;
    }
    int is8 = __syncthreads_or((int)bad);

    // load flags + probe coords (strided, 8 per thread, batched for MLP)
    const float2* lp = (const float2*)locs + b * NN;
    unsigned hit[8];
    float2   pl[8];
    if (is8) {
        const unsigned char* p8 = (const unsigned char*)probe_raw + b * NN;
        #pragma unroll
        for (int j = 0; j < 8; j++) hit[j] = p8[tid + j * 256];
    } else {
        const unsigned* p32 = probe_raw + b * NN;
        #pragma unroll
        for (int j = 0; j < 8; j++) hit[j] = p32[tid + j * 256];
    }
    #pragma unroll
    for (int j = 0; j < 8; j++) pl[j] = lp[tid + j * 256];

    // ---- single-barrier deterministic compaction (warp-major order; probe
    //      order is free because min is order-independent and all 4 quarter
    //      blocks of a batch run the identical algorithm) ----
    int wid = tid >> 5, lid = tid & 31;
    unsigned lmask = (1u << lid) - 1u;
    unsigned bal[8];
    #pragma unroll
    for (int j = 0; j < 8; j++) {
        bal[j] = __ballot_sync(0xFFFFFFFFu, hit[j] != 0u);
        if (lid == 0) s_wc[wid * 8 + j] = __popc(bal[j]);
    }
    __syncthreads();

    int cnt[64];
    #pragma unroll
    for (int k = 0; k < 64; k++) cnt[k] = s_wc[k];

    float* sxyf = (float*)s_xy4;
    float* szf  = (float*)s_zz;
    {
        int pre = 0;
        #pragma unroll
        for (int k = 0; k < 64; k++) {
            int slot = wid * 8 + (k & 7);   // dummy to keep compiler simple
            (void)slot;
        }
        // prefix over entries before this warp's chunks, then per-j writes
        int base_w = 0;
        for (int k = 0; k < wid * 8; k++) base_w += cnt[k];
        int run = base_w;
        #pragma unroll
        for (int j = 0; j < 8; j++) {
            if (hit[j] != 0u) {
                int q  = run + __popc(bal[j] & lmask);
                int pr = q >> 1, c = q & 1;
                sxyf[pr * 4 + c]     = pl[j].x;
                sxyf[pr * 4 + 2 + c] = pl[j].y;
                szf [pr * 2 + c]     = fmaf(pl[j].x, pl[j].x, pl[j].y * pl[j].y);
            }
            run += cnt[wid * 8 + j];
        }
        (void)pre;
    }
    int P = 0;
    #pragma unroll
    for (int k = 0; k < 64; k++) P += cnt[k];
    int Ppad = (P + 63) & ~63;              // probes, multiple of 64
    for (int q = P + tid; q < Ppad; q += 256) {
        int pr = q >> 1, c = q & 1;
        sxyf[pr * 4 + c]     = 0.f;
        sxyf[pr * 4 + 2 + c] = 0.f;
        szf [pr * 2 + c]     = 3.2e38f;
    }

    // node coords + packed query terms (G=4 nodes per thread)
    float2 me[4];
    ull tx2[4], ty2[4];
    float2 m[4];
    #pragma unroll
    for (int g = 0; g < 4; g++) {
        me[g] = lp[nbase + tid + (g << 8)];
        float ntx = -2.f * me[g].x, nty = -2.f * me[g].y;
        tx2[g] = pack2(ntx, ntx);
        ty2[g] = pack2(nty, nty);
        m[g]   = make_float2(3.4e38f, 3.4e38f);
    }
    __syncthreads();

    // min loop over this block's probe quarter
    int npq  = Ppad >> 3;                   // pairs per quarter (mult of 8)
    int i0   = s * npq;
    int iend = i0 + npq;
    const ulonglong2* sxy = (const ulonglong2*)s_xy4;
    for (int i = i0; i < iend; i += 4) {
        ulonglong2 a0 = sxy[i],     a1 = sxy[i + 1];
        ulonglong2 a2 = sxy[i + 2], a3 = sxy[i + 3];
        ull z0 = s_zz[i], z1 = s_zz[i + 1], z2 = s_zz[i + 2], z3 = s_zz[i + 3];
        #pragma unroll
        for (int g = 0; g < 4; g++) {
            mina(m[g], fma2(ty2[g], a0.y, fma2(tx2[g], a0.x, z0)));
            mina(m[g], fma2(ty2[g], a1.y, fma2(tx2[g], a1.x, z1)));
            mina(m[g], fma2(ty2[g], a2.y, fma2(tx2[g], a2.x, z2)));
            mina(m[g], fma2(ty2[g], a3.y, fma2(tx2[g], a3.x, z3)));
        }
    }
    #pragma unroll
    for (int g = 0; g < 4; g++)
        g_minpart[s][b * NN + nbase + tid + (g << 8)] = fminf(m[g].x, m[g].y);
}

// ---------------------------------------------------------------------------
// Kernel 2: coef reduce + final min + sqrt + affine tile write.
// grid = 512 blocks (64-node tiles) x 256 threads -> ~3.5 blocks/SM so store
// latency is hidden; writes stay coalesced STG.128.
// ---------------------------------------------------------------------------
__global__ __launch_bounds__(256) void epi_kernel(
    const float* __restrict__ locs,
    const float* __restrict__ b_out,
    float*       __restrict__ out)
{
    __shared__ float4 s_row[64];
    __shared__ float  s_coef[4][EE];

    int b     = blockIdx.x >> 5;            // 32 tiles per batch
    int nbase = (blockIdx.x & 31) << 6;     // 64-node tile
    int tid   = threadIdx.x;

    {   // folded coefficients, fixed-order reduce (one e per thread)
        float c0 = 0.f, c1 = 0.f, c2 = 0.f, c3 = 0.f;
        #pragma unroll
        for (int c = 0; c < KCH; c++) {
            c0 += g_part[c][0][tid];
            c1 += g_part[c][1][tid];
            c2 += g_part[c][2][tid];
            c3 += g_part[c][3][tid];
        }
        s_coef[0][tid] = c0;
        s_coef[1][tid] = c1;
        s_coef[2][tid] = c2;
        s_coef[3][tid] = c3 + b_out[tid];
    }

    if (tid < 64) {
        int node  = b * NN + nbase + tid;
        float2 me = ((const float2*)locs)[node];
        float p0 = g_minpart[0][node], p1 = g_minpart[1][node];
        float p2 = g_minpart[2][node], p3 = g_minpart[3][node];
        float ms = fminf(fminf(p0, p1), fminf(p2, p3));
        float d2 = fmaxf(fmaf(me.x, me.x, me.y * me.y) + ms, 0.f);
        s_row[tid] = make_float4(me.x, me.y, sqrtf(d2), 0.f);
    }
    __syncthreads();

    int e0   = (tid & 63) << 2;
    int rsub = tid >> 6;
    float4 A0 = *(const float4*)&s_coef[0][e0];
    float4 A1 = *(const float4*)&s_coef[1][e0];
    float4 C  = *(const float4*)&s_coef[2][e0];
    float4 Dv = *(const float4*)&s_coef[3][e0];

    int rowbase = b * NN + nbase;
    #pragma unroll 16
    for (int r0 = 0; r0 < 64; r0 += 4) {
        int r = r0 + rsub;
        float4 rw = s_row[r];
        float4 v;
        v.x = fmaf(rw.x, A0.x, fmaf(rw.y, A1.x, fmaf(rw.z, C.x, Dv.x)));
        v.y = fmaf(rw.x, A0.y, fmaf(rw.y, A1.y, fmaf(rw.z, C.y, Dv.y)));
        v.z = fmaf(rw.x, A0.z, fmaf(rw.y, A1.z, fmaf(rw.z, C.z, Dv.z)));
        v.w = fmaf(rw.x, A0.w, fmaf(rw.y, A1.w, fmaf(rw.z, C.w, Dv.w)));
        *(float4*)(out + (size_t)(rowbase + r) * EE + e0) = v;
    }
}

// ---------------------------------------------------------------------------
extern "C" void kernel_launch(void* const* d_in, const int* in_sizes, int n_in,
                              void* d_out, int out_size)
{
    const float*    locs   = (const float*)d_in[0];
    const unsigned* probe  = (const unsigned*)d_in[1];
    const float*    W_node = (const float*)d_in[2];
    const float*    b_node = (const float*)d_in[3];
    const float*    W_dist = (const float*)d_in[4];
    const float*    b_dist = (const float*)d_in[5];
    const float*    W_out  = (const float*)d_in[6];
    const float*    b_out  = (const float*)d_in[7];
    float* out = (float*)d_out;

    main1_kernel<<<128 + KCH, 256>>>(locs, probe, W_node, b_node, W_dist, b_dist, W_out);
    epi_kernel<<<512, 256>>>(locs, b_out, out);
}

// round 7
// speedup vs baseline: 1.3561x; 1.3561x over previous
#include <cuda_runtime.h>

#define BB 16
#define NN 2048
#define EE 256

typedef unsigned long long ull;

// Scratch (__device__ globals; allocation-free rule)
__device__ float g_coef[5][EE];          // [0]=A0 [1]=A1 [2]=Dtop [3]=C [4]=Dbot+b_out
__device__ float g_minpart[4][BB * NN];  // per-quarter partial min scores (512KB)

// ---- f32x2 helpers ---------------------------------------------------------
__device__ __forceinline__ ull fma2(ull a, ull b, ull c) {
    ull d;
    asm("fma.rn.f32x2 %0, %1, %2, %3;" : "=l"(d) : "l"(a), "l"(b), "l"(c));
    return d;
}
union F2U { ull u; float2 f; };
__device__ __forceinline__ ull pack2(float lo, float hi) {
    F2U t; t.f = make_float2(lo, hi); return t.u;
}
__device__ __forceinline__ void mina(float2& m, ull v) {
    F2U t; t.u = v;
    m.x = fminf(m.x, t.f.x);
    m.y = fminf(m.y, t.f.y);
}

// ---------------------------------------------------------------------------
// Kernel 1: grid = 130 blocks, 256 threads.
//   blocks [0,128):  (tile, quarter) min blocks: register-clean deterministic
//                    compaction into shared pair-SoA, then packed-f32x2 min
//                    over this block's probe quarter for 1024 nodes (G=4).
//   block 128:       final coefficients, top half of W_out  (A0, A1, Dtop)
//   block 129:       final coefficients, bottom half        (C, Dbot + b_out)
// ---------------------------------------------------------------------------
__global__ __launch_bounds__(256) void main1_kernel(
    const float*    __restrict__ locs,
    const unsigned* __restrict__ probe_raw,
    const float*    __restrict__ W_node,
    const float*    __restrict__ b_node,
    const float*    __restrict__ W_dist,
    const float*    __restrict__ b_dist,
    const float*    __restrict__ W_out,
    const float*    __restrict__ b_out)
{
    int blk = blockIdx.x;
    int tid = threadIdx.x;

    if (blk == 128) {            // top half coefficients
        int e = tid;
        float a0 = 0.f, a1 = 0.f, dt = 0.f;
        #pragma unroll 8
        for (int k = 0; k < EE; k++) {
            float wt = W_out[k * EE + e];
            a0 = fmaf(W_node[k],      wt, a0);
            a1 = fmaf(W_node[EE + k], wt, a1);
            dt = fmaf(b_node[k],      wt, dt);
        }
        g_coef[0][e] = a0;
        g_coef[1][e] = a1;
        g_coef[2][e] = dt;
        return;
    }
    if (blk == 129) {            // bottom half coefficients
        int e = tid;
        float cc = 0.f, db = 0.f;
        #pragma unroll 8
        for (int k = 0; k < EE; k++) {
            float wb = W_out[(EE + k) * EE + e];
            cc = fmaf(W_dist[k], wb, cc);
            db = fmaf(b_dist[k], wb, db);
        }
        g_coef[3][e] = cc;
        g_coef[4][e] = db + b_out[e];
        return;
    }

    // ---- min block: (tile, quarter) ----
    int tile  = blk >> 2;               // 0..31 (1024-node tiles)
    int s     = blk & 3;                // probe quarter
    int b     = tile >> 1;              // batch
    int nbase = (tile & 1) << 10;

    __shared__ float4 s_xy4[NN / 2];    // pair-SoA (x0,x1,y0,y1), 16KB
    __shared__ ull    s_zz [NN / 2];    // pair (z0,z1), 8KB
    __shared__ int    s_wt[8];          // per-warp compaction totals

    // dtype detect on 512 words (valid reads under both candidate layouts)
    bool bad = false;
    #pragma unroll
    for (int j = 0; j < 2; j++) {
        unsigned v = probe_raw[b * 512 + j * 256 + tid];
        if (v != 0u && v != 1u && v != 0x3F800000u) bad = true;
    }
    int is8 = __syncthreads_or((int)bad);

    // wide loads: thread tid owns probes [tid*8, tid*8+8)
    unsigned hit[8];
    if (is8) {
        uint2 w = ((const uint2*)((const char*)probe_raw + (size_t)b * NN))[tid];
        hit[0] =  w.x        & 0xFFu;
        hit[1] = (w.x >>  8) & 0xFFu;
        hit[2] = (w.x >> 16) & 0xFFu;
        hit[3] = (w.x >> 24) & 0xFFu;
        hit[4] =  w.y        & 0xFFu;
        hit[5] = (w.y >>  8) & 0xFFu;
        hit[6] = (w.y >> 16) & 0xFFu;
        hit[7] = (w.y >> 24) & 0xFFu;
    } else {
        const uint4* p = (const uint4*)(probe_raw + (size_t)b * NN);
        uint4 w0 = p[tid * 2], w1 = p[tid * 2 + 1];
        hit[0] = w0.x; hit[1] = w0.y; hit[2] = w0.z; hit[3] = w0.w;
        hit[4] = w1.x; hit[5] = w1.y; hit[6] = w1.z; hit[7] = w1.w;
    }
    const float2* lp  = (const float2*)locs + b * NN;
    const float4* lp4 = (const float4*)lp;
    float4 l0 = lp4[tid * 4],     l1 = lp4[tid * 4 + 1];
    float4 l2 = lp4[tid * 4 + 2], l3 = lp4[tid * 4 + 3];
    float2 pl[8] = {
        {l0.x, l0.y}, {l0.z, l0.w}, {l1.x, l1.y}, {l1.z, l1.w},
        {l2.x, l2.y}, {l2.z, l2.w}, {l3.x, l3.y}, {l3.z, l3.w}
    };

    // deterministic compaction: warp-major, then j, then lane. Ballots are
    // warp-uniform so running offsets are register-only; shared holds only
    // the 8 per-warp totals.
    int wid = tid >> 5, lid = tid & 31;
    unsigned lmask = (1u << lid) - 1u;
    unsigned bal[8];
    #pragma unroll
    for (int j = 0; j < 8; j++)
        bal[j] = __ballot_sync(0xFFFFFFFFu, hit[j] != 0u);
    if (lid == 0) {
        int t = 0;
        #pragma unroll
        for (int j = 0; j < 8; j++) t += __popc(bal[j]);
        s_wt[wid] = t;
    }
    __syncthreads();

    int base = 0, P = 0;
    #pragma unroll
    for (int w = 0; w < 8; w++) {
        int t = s_wt[w];
        if (w < wid) base += t;
        P += t;
    }

    float* sxyf = (float*)s_xy4;
    float* szf  = (float*)s_zz;
    {
        int run = base;
        #pragma unroll
        for (int j = 0; j < 8; j++) {
            if (hit[j] != 0u) {
                int q  = run + __popc(bal[j] & lmask);
                int pr = q >> 1, c = q & 1;
                sxyf[pr * 4 + c]     = pl[j].x;
                sxyf[pr * 4 + 2 + c] = pl[j].y;
                szf [pr * 2 + c]     = fmaf(pl[j].x, pl[j].x, pl[j].y * pl[j].y);
            }
            run += __popc(bal[j]);    // warp-uniform, register-only
        }
    }
    int Ppad = (P + 63) & ~63;        // probes, multiple of 64
    for (int q = P + tid; q < Ppad; q += 256) {
        int pr = q >> 1, c = q & 1;
        sxyf[pr * 4 + c]     = 0.f;
        sxyf[pr * 4 + 2 + c] = 0.f;
        szf [pr * 2 + c]     = 3.2e38f;
    }

    // node coords + packed query terms (G=4 nodes per thread)
    float2 me[4];
    ull tx2[4], ty2[4];
    float2 m[4];
    #pragma unroll
    for (int g = 0; g < 4; g++) {
        me[g] = lp[nbase + tid + (g << 8)];
        float ntx = -2.f * me[g].x, nty = -2.f * me[g].y;
        tx2[g] = pack2(ntx, ntx);
        ty2[g] = pack2(nty, nty);
        m[g]   = make_float2(3.4e38f, 3.4e38f);
    }
    __syncthreads();

    // min loop over this block's probe quarter
    int npq  = Ppad >> 3;             // pairs per quarter (multiple of 8)
    int i0   = s * npq;
    int iend = i0 + npq;
    const ulonglong2* sxy = (const ulonglong2*)s_xy4;
    for (int i = i0; i < iend; i += 4) {
        ulonglong2 a0 = sxy[i],     a1 = sxy[i + 1];
        ulonglong2 a2 = sxy[i + 2], a3 = sxy[i + 3];
        ull z0 = s_zz[i], z1 = s_zz[i + 1], z2 = s_zz[i + 2], z3 = s_zz[i + 3];
        #pragma unroll
        for (int g = 0; g < 4; g++) {
            mina(m[g], fma2(ty2[g], a0.y, fma2(tx2[g], a0.x, z0)));
            mina(m[g], fma2(ty2[g], a1.y, fma2(tx2[g], a1.x, z1)));
            mina(m[g], fma2(ty2[g], a2.y, fma2(tx2[g], a2.x, z2)));
            mina(m[g], fma2(ty2[g], a3.y, fma2(tx2[g], a3.x, z3)));
        }
    }
    #pragma unroll
    for (int g = 0; g < 4; g++)
        g_minpart[s][b * NN + nbase + tid + (g << 8)] = fminf(m[g].x, m[g].y);
}

// ---------------------------------------------------------------------------
// Kernel 2: final min + sqrt + affine tile write.
// grid = 256 blocks (128-node tiles) x 256 threads. Per-block coef cost is
// just 5 LDG.128 (final coefs precomputed in kernel1) -> minimal fixed cost.
// ---------------------------------------------------------------------------
__global__ __launch_bounds__(256) void epi_kernel(
    const float* __restrict__ locs, float* __restrict__ out)
{
    __shared__ float4 s_row[128];

    int b     = blockIdx.x >> 4;          // 16 tiles per batch
    int nbase = (blockIdx.x & 15) << 7;   // 128-node tile
    int tid   = threadIdx.x;

    int e0 = (tid & 63) << 2;
    float4 A0 = *(const float4*)&g_coef[0][e0];
    float4 A1 = *(const float4*)&g_coef[1][e0];
    float4 Dt = *(const float4*)&g_coef[2][e0];
    float4 C  = *(const float4*)&g_coef[3][e0];
    float4 Db = *(const float4*)&g_coef[4][e0];
    float4 Dv = make_float4(Dt.x + Db.x, Dt.y + Db.y, Dt.z + Db.z, Dt.w + Db.w);

    if (tid < 128) {
        int node  = b * NN + nbase + tid;
        float2 me = ((const float2*)locs)[node];
        float p0 = g_minpart[0][node], p1 = g_minpart[1][node];
        float p2 = g_minpart[2][node], p3 = g_minpart[3][node];
        float ms = fminf(fminf(p0, p1), fminf(p2, p3));
        float d2 = fmaxf(fmaf(me.x, me.x, me.y * me.y) + ms, 0.f);
        s_row[tid] = make_float4(me.x, me.y, sqrtf(d2), 0.f);
    }
    __syncthreads();

    int rsub    = tid >> 6;
    int rowbase = b * NN + nbase;
    #pragma unroll 8
    for (int r0 = 0; r0 < 128; r0 += 4) {
        int r = r0 + rsub;
        float4 rw = s_row[r];
        float4 v;
        v.x = fmaf(rw.x, A0.x, fmaf(rw.y, A1.x, fmaf(rw.z, C.x, Dv.x)));
        v.y = fmaf(rw.x, A0.y, fmaf(rw.y, A1.y, fmaf(rw.z, C.y, Dv.y)));
        v.z = fmaf(rw.x, A0.z, fmaf(rw.y, A1.z, fmaf(rw.z, C.z, Dv.z)));
        v.w = fmaf(rw.x, A0.w, fmaf(rw.y, A1.w, fmaf(rw.z, C.w, Dv.w)));
        *(float4*)(out + (size_t)(rowbase + r) * EE + e0) = v;
    }
}

// ---------------------------------------------------------------------------
extern "C" void kernel_launch(void* const* d_in, const int* in_sizes, int n_in,
                              void* d_out, int out_size)
{
    const float*    locs   = (const float*)d_in[0];
    const unsigned* probe  = (const unsigned*)d_in[1];
    const float*    W_node = (const float*)d_in[2];
    const float*    b_node = (const float*)d_in[3];
    const float*    W_dist = (const float*)d_in[4];
    const float*    b_dist = (const float*)d_in[5];
    const float*    W_out  = (const float*)d_in[6];
    const float*    b_out  = (const float*)d_in[7];
    float* out = (float*)d_out;

    main1_kernel<<<130, 256>>>(locs, probe, W_node, b_node, W_dist, b_dist, W_out, b_out);
    epi_kernel<<<256, 256>>>(locs, out);
}

// round 9
// speedup vs baseline: 1.4338x; 1.0574x over previous
#include <cuda_runtime.h>

#define BB 16
#define NN 2048
#define EE 256

typedef unsigned long long ull;

// Scratch (__device__ globals; allocation-free rule)
__device__ float g_coef[5][EE];          // [0]=A0 [1]=A1 [2]=Dtop [3]=C [4]=Dbot+b_out
__device__ float g_minpart[4][BB * NN];  // per-quarter partial min scores (512KB)

// ---- f32x2 helpers ---------------------------------------------------------
__device__ __forceinline__ ull fma2(ull a, ull b, ull c) {
    ull d;
    asm("fma.rn.f32x2 %0, %1, %2, %3;" : "=l"(d) : "l"(a), "l"(b), "l"(c));
    return d;
}
union F2U { ull u; float2 f; };
__device__ __forceinline__ ull pack2(float lo, float hi) {
    F2U t; t.f = make_float2(lo, hi); return t.u;
}
__device__ __forceinline__ void mina(float2& m, ull v) {
    F2U t; t.u = v;
    m.x = fminf(m.x, t.f.x);
    m.y = fminf(m.y, t.f.y);
}

// ---------------------------------------------------------------------------
// Kernel 1: grid = 144 blocks, 256 threads.
//   blocks [0,128):   (tile, quarter) min blocks (compaction + packed min).
//   blocks [128,136): top-half coefs: block t owns e in [t*32, t*32+32).
//                     256 thr = 32 e x 8 k-groups; 32 k's per thread; fixed-
//                     order 8-way reduce through shared -> FINAL A0,A1,Dtop.
//   blocks [136,144): bottom-half coefs likewise -> FINAL C, Dbot+b_out.
// ---------------------------------------------------------------------------
__global__ __launch_bounds__(256) void main1_kernel(
    const float*    __restrict__ locs,
    const unsigned* __restrict__ probe_raw,
    const float*    __restrict__ W_node,
    const float*    __restrict__ b_node,
    const float*    __restrict__ W_dist,
    const float*    __restrict__ b_dist,
    const float*    __restrict__ W_out,
    const float*    __restrict__ b_out)
{
    int blk = blockIdx.x;
    int tid = threadIdx.x;

    if (blk >= 128) {
        __shared__ float s_red[3][8][32];
        int top    = blk < 136;
        int t      = top ? (blk - 128) : (blk - 136);
        int elocal = tid & 31;
        int kg     = tid >> 5;
        int e      = t * 32 + elocal;
        int k0     = kg * 32;

        float a0 = 0.f, a1 = 0.f, dd = 0.f;
        if (top) {
            #pragma unroll 8
            for (int kk = 0; kk < 32; kk++) {
                int k = k0 + kk;
                float wt = W_out[k * EE + e];
                a0 = fmaf(W_node[k],      wt, a0);
                a1 = fmaf(W_node[EE + k], wt, a1);
                dd = fmaf(b_node[k],      wt, dd);
            }
        } else {
            #pragma unroll 8
            for (int kk = 0; kk < 32; kk++) {
                int k = k0 + kk;
                float wb = W_out[(EE + k) * EE + e];
                a0 = fmaf(W_dist[k], wb, a0);   // -> C
                dd = fmaf(b_dist[k], wb, dd);   // -> Dbot
            }
        }
        s_red[0][kg][elocal] = a0;
        s_red[1][kg][elocal] = a1;
        s_red[2][kg][elocal] = dd;
        __syncthreads();
        if (tid < 32) {
            float r0 = 0.f, r1 = 0.f, r2 = 0.f;
            #pragma unroll
            for (int g = 0; g < 8; g++) {       // fixed order
                r0 += s_red[0][g][tid];
                r1 += s_red[1][g][tid];
                r2 += s_red[2][g][tid];
            }
            int eo = t * 32 + tid;
            if (top) {
                g_coef[0][eo] = r0;
                g_coef[1][eo] = r1;
                g_coef[2][eo] = r2;
            } else {
                g_coef[3][eo] = r0;
                g_coef[4][eo] = r2 + b_out[eo];
            }
        }
        return;
    }

    // ---- min block: (tile, quarter) ----
    int tile  = blk >> 2;               // 0..31 (1024-node tiles)
    int s     = blk & 3;                // probe quarter
    int b     = tile >> 1;              // batch
    int nbase = (tile & 1) << 10;

    __shared__ float4 s_xy4[NN / 2];    // pair-SoA (x0,x1,y0,y1), 16KB
    __shared__ ull    s_zz [NN / 2];    // pair (z0,z1), 8KB
    __shared__ int    s_wt[8];          // per-warp compaction totals

    // dtype detect on 512 words (valid reads under both candidate layouts)
    bool bad = false;
    #pragma unroll
    for (int j = 0; j < 2; j++) {
        unsigned v = probe_raw[b * 512 + j * 256 + tid];
        if (v != 0u && v != 1u && v != 0x3F800000u) bad = true;
    }
    int is8 = __syncthreads_or((int)bad);

    // wide loads: thread tid owns probes [tid*8, tid*8+8)
    unsigned hit[8];
    if (is8) {
        uint2 w = ((const uint2*)((const char*)probe_raw + (size_t)b * NN))[tid];
        hit[0] =  w.x        & 0xFFu;
        hit[1] = (w.x >>  8) & 0xFFu;
        hit[2] = (w.x >> 16) & 0xFFu;
        hit[3] = (w.x >> 24) & 0xFFu;
        hit[4] =  w.y        & 0xFFu;
        hit[5] = (w.y >>  8) & 0xFFu;
        hit[6] = (w.y >> 16) & 0xFFu;
        hit[7] = (w.y >> 24) & 0xFFu;
    } else {
        const uint4* p = (const uint4*)(probe_raw + (size_t)b * NN);
        uint4 w0 = p[tid * 2], w1 = p[tid * 2 + 1];
        hit[0] = w0.x; hit[1] = w0.y; hit[2] = w0.z; hit[3] = w0.w;
        hit[4] = w1.x; hit[5] = w1.y; hit[6] = w1.z; hit[7] = w1.w;
    }
    const float2* lp  = (const float2*)locs + b * NN;
    const float4* lp4 = (const float4*)lp;
    float4 l0 = lp4[tid * 4],     l1 = lp4[tid * 4 + 1];
    float4 l2 = lp4[tid * 4 + 2], l3 = lp4[tid * 4 + 3];
    float2 pl[8] = {
        {l0.x, l0.y}, {l0.z, l0.w}, {l1.x, l1.y}, {l1.z, l1.w},
        {l2.x, l2.y}, {l2.z, l2.w}, {l3.x, l3.y}, {l3.z, l3.w}
    };

    // deterministic compaction: warp-major, then j, then lane. Ballots are
    // warp-uniform so running offsets are register-only.
    int wid = tid >> 5, lid = tid & 31;
    unsigned lmask = (1u << lid) - 1u;
    unsigned bal[8];
    #pragma unroll
    for (int j = 0; j < 8; j++)
        bal[j] = __ballot_sync(0xFFFFFFFFu, hit[j] != 0u);
    if (lid == 0) {
        int t = 0;
        #pragma unroll
        for (int j = 0; j < 8; j++) t += __popc(bal[j]);
        s_wt[wid] = t;
    }
    __syncthreads();

    int base = 0, P = 0;
    #pragma unroll
    for (int w = 0; w < 8; w++) {
        int t = s_wt[w];
        if (w < wid) base += t;
        P += t;
    }

    float* sxyf = (float*)s_xy4;
    float* szf  = (float*)s_zz;
    {
        int run = base;
        #pragma unroll
        for (int j = 0; j < 8; j++) {
            if (hit[j] != 0u) {
                int q  = run + __popc(bal[j] & lmask);
                int pr = q >> 1, c = q & 1;
                sxyf[pr * 4 + c]     = pl[j].x;
                sxyf[pr * 4 + 2 + c] = pl[j].y;
                szf [pr * 2 + c]     = fmaf(pl[j].x, pl[j].x, pl[j].y * pl[j].y);
            }
            run += __popc(bal[j]);    // warp-uniform, register-only
        }
    }
    int Ppad = (P + 63) & ~63;        // probes, multiple of 64
    for (int q = P + tid; q < Ppad; q += 256) {
        int pr = q >> 1, c = q & 1;
        sxyf[pr * 4 + c]     = 0.f;
        sxyf[pr * 4 + 2 + c] = 0.f;
        szf [pr * 2 + c]     = 3.2e38f;
    }

    // node coords + packed query terms (G=4 nodes per thread)
    float2 me[4];
    ull tx2[4], ty2[4];
    float2 m[4];
    #pragma unroll
    for (int g = 0; g < 4; g++) {
        me[g] = lp[nbase + tid + (g << 8)];
        float ntx = -2.f * me[g].x, nty = -2.f * me[g].y;
        tx2[g] = pack2(ntx, ntx);
        ty2[g] = pack2(nty, nty);
        m[g]   = make_float2(3.4e38f, 3.4e38f);
    }
    __syncthreads();

    // min loop over this block's probe quarter
    int npq  = Ppad >> 3;             // pairs per quarter (multiple of 8)
    int i0   = s * npq;
    int iend = i0 + npq;
    const ulonglong2* sxy = (const ulonglong2*)s_xy4;
    for (int i = i0; i < iend; i += 4) {
        ulonglong2 a0 = sxy[i],     a1 = sxy[i + 1];
        ulonglong2 a2 = sxy[i + 2], a3 = sxy[i + 3];
        ull z0 = s_zz[i], z1 = s_zz[i + 1], z2 = s_zz[i + 2], z3 = s_zz[i + 3];
        #pragma unroll
        for (int g = 0; g < 4; g++) {
            mina(m[g], fma2(ty2[g], a0.y, fma2(tx2[g], a0.x, z0)));
            mina(m[g], fma2(ty2[g], a1.y, fma2(tx2[g], a1.x, z1)));
            mina(m[g], fma2(ty2[g], a2.y, fma2(tx2[g], a2.x, z2)));
            mina(m[g], fma2(ty2[g], a3.y, fma2(tx2[g], a3.x, z3)));
        }
    }
    #pragma unroll
    for (int g = 0; g < 4; g++)
        g_minpart[s][b * NN + nbase + tid + (g << 8)] = fminf(m[g].x, m[g].y);
}

// ---------------------------------------------------------------------------
// Kernel 2: final min + sqrt + affine tile write.
// grid = 512 blocks (64-node tiles) x 256 threads -> ~3.5 blocks/SM, ~28
// resident warps to keep stores in flight. Per-block fixed cost: 5 LDG.128.
// ---------------------------------------------------------------------------
__global__ __launch_bounds__(256) void epi_kernel(
    const float* __restrict__ locs, float* __restrict__ out)
{
    __shared__ float4 s_row[64];

    int b     = blockIdx.x >> 5;          // 32 tiles per batch
    int nbase = (blockIdx.x & 31) << 6;   // 64-node tile
    int tid   = threadIdx.x;

    int e0 = (tid & 63) << 2;
    float4 A0 = *(const float4*)&g_coef[0][e0];
    float4 A1 = *(const float4*)&g_coef[1][e0];
    float4 Dt = *(const float4*)&g_coef[2][e0];
    float4 C  = *(const float4*)&g_coef[3][e0];
    float4 Db = *(const float4*)&g_coef[4][e0];
    float4 Dv = make_float4(Dt.x + Db.x, Dt.y + Db.y, Dt.z + Db.z, Dt.w + Db.w);

    if (tid < 64) {
        int node  = b * NN + nbase + tid;
        float2 me = ((const float2*)locs)[node];
        float p0 = g_minpart[0][node], p1 = g_minpart[1][node];
        float p2 = g_minpart[2][node], p3 = g_minpart[3][node];
        float ms = fminf(fminf(p0, p1), fminf(p2, p3));
        float d2 = fmaxf(fmaf(me.x, me.x, me.y * me.y) + ms, 0.f);
        s_row[tid] = make_float4(me.x, me.y, sqrtf(d2), 0.f);
    }
    __syncthreads();

    int rsub    = tid >> 6;
    int rowbase = b * NN + nbase;
    #pragma unroll 16
    for (int r0 = 0; r0 < 64; r0 += 4) {
        int r = r0 + rsub;
        float4 rw = s_row[r];
        float4 v;
        v.x = fmaf(rw.x, A0.x, fmaf(rw.y, A1.x, fmaf(rw.z, C.x, Dv.x)));
        v.y = fmaf(rw.x, A0.y, fmaf(rw.y, A1.y, fmaf(rw.z, C.y, Dv.y)));
        v.z = fmaf(rw.x, A0.z, fmaf(rw.y, A1.z, fmaf(rw.z, C.z, Dv.z)));
        v.w = fmaf(rw.x, A0.w, fmaf(rw.y, A1.w, fmaf(rw.z, C.w, Dv.w)));
        *(float4*)(out + (size_t)(rowbase + r) * EE + e0) = v;
    }
}

// ---------------------------------------------------------------------------
extern "C" void kernel_launch(void* const* d_in, const int* in_sizes, int n_in,
                              void* d_out, int out_size)
{
    const float*    locs   = (const float*)d_in[0];
    const unsigned* probe  = (const unsigned*)d_in[1];
    const float*    W_node = (const float*)d_in[2];
    const float*    b_node = (const float*)d_in[3];
    const float*    W_dist = (const float*)d_in[4];
    const float*    b_dist = (const float*)d_in[5];
    const float*    W_out  = (const float*)d_in[6];
    const float*    b_out  = (const float*)d_in[7];
    float* out = (float*)d_out;

    main1_kernel<<<144, 256>>>(locs, probe, W_node, b_node, W_dist, b_dist, W_out, b_out);
    epi_kernel<<<512, 256>>>(locs, out);
}

// round 10
// speedup vs baseline: 1.6869x; 1.1765x over previous
#include <cuda_runtime.h>

#define BB 16
#define NN 2048
#define EE 256

typedef unsigned long long ull;

// Scratch (__device__ globals; allocation-free rule)
__device__ float g_coef[5][EE];          // [0]=A0 [1]=A1 [2]=Dtop [3]=C [4]=Dbot+b_out
__device__ float g_minpart[4][BB * NN];  // per-quarter partial min scores (512KB)

// ---- f32x2 helpers ---------------------------------------------------------
__device__ __forceinline__ ull fma2(ull a, ull b, ull c) {
    ull d;
    asm("fma.rn.f32x2 %0, %1, %2, %3;" : "=l"(d) : "l"(a), "l"(b), "l"(c));
    return d;
}
union F2U { ull u; float2 f; };
__device__ __forceinline__ ull pack2(float lo, float hi) {
    F2U t; t.f = make_float2(lo, hi); return t.u;
}
__device__ __forceinline__ void mina(float2& m, ull v) {
    F2U t; t.u = v;
    m.x = fminf(m.x, t.f.x);
    m.y = fminf(m.y, t.f.y);
}
__device__ __forceinline__ unsigned smem_u32(const void* p) {
    unsigned a;
    asm("{ .reg .u64 t; cvta.to.shared.u64 t, %1; cvt.u32.u64 %0, t; }"
        : "=r"(a) : "l"(p));
    return a;
}

// ---------------------------------------------------------------------------
// Kernel 1: grid = 144 blocks, 256 threads.  (identical to R9)
//   blocks [0,128):   (tile, quarter) min blocks (compaction + packed min).
//   blocks [128,136): top-half coefs (final A0, A1, Dtop).
//   blocks [136,144): bottom-half coefs (final C, Dbot + b_out).
// ---------------------------------------------------------------------------
__global__ __launch_bounds__(256) void main1_kernel(
    const float*    __restrict__ locs,
    const unsigned* __restrict__ probe_raw,
    const float*    __restrict__ W_node,
    const float*    __restrict__ b_node,
    const float*    __restrict__ W_dist,
    const float*    __restrict__ b_dist,
    const float*    __restrict__ W_out,
    const float*    __restrict__ b_out)
{
    int blk = blockIdx.x;
    int tid = threadIdx.x;

    if (blk >= 128) {
        __shared__ float s_red[3][8][32];
        int top    = blk < 136;
        int t      = top ? (blk - 128) : (blk - 136);
        int elocal = tid & 31;
        int kg     = tid >> 5;
        int e      = t * 32 + elocal;
        int k0     = kg * 32;

        float a0 = 0.f, a1 = 0.f, dd = 0.f;
        if (top) {
            #pragma unroll 8
            for (int kk = 0; kk < 32; kk++) {
                int k = k0 + kk;
                float wt = W_out[k * EE + e];
                a0 = fmaf(W_node[k],      wt, a0);
                a1 = fmaf(W_node[EE + k], wt, a1);
                dd = fmaf(b_node[k],      wt, dd);
            }
        } else {
            #pragma unroll 8
            for (int kk = 0; kk < 32; kk++) {
                int k = k0 + kk;
                float wb = W_out[(EE + k) * EE + e];
                a0 = fmaf(W_dist[k], wb, a0);   // -> C
                dd = fmaf(b_dist[k], wb, dd);   // -> Dbot
            }
        }
        s_red[0][kg][elocal] = a0;
        s_red[1][kg][elocal] = a1;
        s_red[2][kg][elocal] = dd;
        __syncthreads();
        if (tid < 32) {
            float r0 = 0.f, r1 = 0.f, r2 = 0.f;
            #pragma unroll
            for (int g = 0; g < 8; g++) {       // fixed order
                r0 += s_red[0][g][tid];
                r1 += s_red[1][g][tid];
                r2 += s_red[2][g][tid];
            }
            int eo = t * 32 + tid;
            if (top) {
                g_coef[0][eo] = r0;
                g_coef[1][eo] = r1;
                g_coef[2][eo] = r2;
            } else {
                g_coef[3][eo] = r0;
                g_coef[4][eo] = r2 + b_out[eo];
            }
        }
        return;
    }

    // ---- min block: (tile, quarter) ----
    int tile  = blk >> 2;
    int s     = blk & 3;
    int b     = tile >> 1;
    int nbase = (tile & 1) << 10;

    __shared__ float4 s_xy4[NN / 2];
    __shared__ ull    s_zz [NN / 2];
    __shared__ int    s_wt[8];

    bool bad = false;
    #pragma unroll
    for (int j = 0; j < 2; j++) {
        unsigned v = probe_raw[b * 512 + j * 256 + tid];
        if (v != 0u && v != 1u && v != 0x3F800000u) bad = true;
    }
    int is8 = __syncthreads_or((int)bad);

    unsigned hit[8];
    if (is8) {
        uint2 w = ((const uint2*)((const char*)probe_raw + (size_t)b * NN))[tid];
        hit[0] =  w.x        & 0xFFu;
        hit[1] = (w.x >>  8) & 0xFFu;
        hit[2] = (w.x >> 16) & 0xFFu;
        hit[3] = (w.x >> 24) & 0xFFu;
        hit[4] =  w.y        & 0xFFu;
        hit[5] = (w.y >>  8) & 0xFFu;
        hit[6] = (w.y >> 16) & 0xFFu;
        hit[7] = (w.y >> 24) & 0xFFu;
    } else {
        const uint4* p = (const uint4*)(probe_raw + (size_t)b * NN);
        uint4 w0 = p[tid * 2], w1 = p[tid * 2 + 1];
        hit[0] = w0.x; hit[1] = w0.y; hit[2] = w0.z; hit[3] = w0.w;
        hit[4] = w1.x; hit[5] = w1.y; hit[6] = w1.z; hit[7] = w1.w;
    }
    const float2* lp  = (const float2*)locs + b * NN;
    const float4* lp4 = (const float4*)lp;
    float4 l0 = lp4[tid * 4],     l1 = lp4[tid * 4 + 1];
    float4 l2 = lp4[tid * 4 + 2], l3 = lp4[tid * 4 + 3];
    float2 pl[8] = {
        {l0.x, l0.y}, {l0.z, l0.w}, {l1.x, l1.y}, {l1.z, l1.w},
        {l2.x, l2.y}, {l2.z, l2.w}, {l3.x, l3.y}, {l3.z, l3.w}
    };

    int wid = tid >> 5, lid = tid & 31;
    unsigned lmask = (1u << lid) - 1u;
    unsigned bal[8];
    #pragma unroll
    for (int j = 0; j < 8; j++)
        bal[j] = __ballot_sync(0xFFFFFFFFu, hit[j] != 0u);
    if (lid == 0) {
        int t = 0;
        #pragma unroll
        for (int j = 0; j < 8; j++) t += __popc(bal[j]);
        s_wt[wid] = t;
    }
    __syncthreads();

    int base = 0, P = 0;
    #pragma unroll
    for (int w = 0; w < 8; w++) {
        int t = s_wt[w];
        if (w < wid) base += t;
        P += t;
    }

    float* sxyf = (float*)s_xy4;
    float* szf  = (float*)s_zz;
    {
        int run = base;
        #pragma unroll
        for (int j = 0; j < 8; j++) {
            if (hit[j] != 0u) {
                int q  = run + __popc(bal[j] & lmask);
                int pr = q >> 1, c = q & 1;
                sxyf[pr * 4 + c]     = pl[j].x;
                sxyf[pr * 4 + 2 + c] = pl[j].y;
                szf [pr * 2 + c]     = fmaf(pl[j].x, pl[j].x, pl[j].y * pl[j].y);
            }
            run += __popc(bal[j]);
        }
    }
    int Ppad = (P + 63) & ~63;
    for (int q = P + tid; q < Ppad; q += 256) {
        int pr = q >> 1, c = q & 1;
        sxyf[pr * 4 + c]     = 0.f;
        sxyf[pr * 4 + 2 + c] = 0.f;
        szf [pr * 2 + c]     = 3.2e38f;
    }

    float2 me[4];
    ull tx2[4], ty2[4];
    float2 m[4];
    #pragma unroll
    for (int g = 0; g < 4; g++) {
        me[g] = lp[nbase + tid + (g << 8)];
        float ntx = -2.f * me[g].x, nty = -2.f * me[g].y;
        tx2[g] = pack2(ntx, ntx);
        ty2[g] = pack2(nty, nty);
        m[g]   = make_float2(3.4e38f, 3.4e38f);
    }
    __syncthreads();

    int npq  = Ppad >> 3;
    int i0   = s * npq;
    int iend = i0 + npq;
    const ulonglong2* sxy = (const ulonglong2*)s_xy4;
    for (int i = i0; i < iend; i += 4) {
        ulonglong2 a0 = sxy[i],     a1 = sxy[i + 1];
        ulonglong2 a2 = sxy[i + 2], a3 = sxy[i + 3];
        ull z0 = s_zz[i], z1 = s_zz[i + 1], z2 = s_zz[i + 2], z3 = s_zz[i + 3];
        #pragma unroll
        for (int g = 0; g < 4; g++) {
            mina(m[g], fma2(ty2[g], a0.y, fma2(tx2[g], a0.x, z0)));
            mina(m[g], fma2(ty2[g], a1.y, fma2(tx2[g], a1.x, z1)));
            mina(m[g], fma2(ty2[g], a2.y, fma2(tx2[g], a2.x, z2)));
            mina(m[g], fma2(ty2[g], a3.y, fma2(tx2[g], a3.x, z3)));
        }
    }
    #pragma unroll
    for (int g = 0; g < 4; g++)
        g_minpart[s][b * NN + nbase + tid + (g << 8)] = fminf(m[g].x, m[g].y);
}

// ---------------------------------------------------------------------------
// Kernel 2: final min + sqrt + affine, with BULK TMA stores.
// grid = 128 blocks x 256 threads; block = 256 contiguous rows (256KB out).
// 4 chunks of 64 rows (64KB), double-buffered in 2x64KB dynamic smem:
//   compute chunk -> fence.proxy.async -> cp.async.bulk -> commit;
//   wait_group 1 gates buffer reuse. Store drain overlaps next chunk compute.
// ---------------------------------------------------------------------------
__global__ __launch_bounds__(256) void epi_kernel(
    const float* __restrict__ locs, float* __restrict__ out)
{
    extern __shared__ char dynbuf[];          // 2 x 64KB staging
    __shared__ float4 s_row[256];             // (x, y, md) per row

    int blk  = blockIdx.x;
    int tid  = threadIdx.x;
    int row0 = blk << 8;                      // first global row of this block

    int e0 = (tid & 63) << 2;
    float4 A0 = *(const float4*)&g_coef[0][e0];
    float4 A1 = *(const float4*)&g_coef[1][e0];
    float4 Dt = *(const float4*)&g_coef[2][e0];
    float4 C  = *(const float4*)&g_coef[3][e0];
    float4 Db = *(const float4*)&g_coef[4][e0];
    float4 Dv = make_float4(Dt.x + Db.x, Dt.y + Db.y, Dt.z + Db.z, Dt.w + Db.w);

    {   // md for this block's 256 rows
        int node  = row0 + tid;
        float2 me = ((const float2*)locs)[node];
        float p0 = g_minpart[0][node], p1 = g_minpart[1][node];
        float p2 = g_minpart[2][node], p3 = g_minpart[3][node];
        float ms = fminf(fminf(p0, p1), fminf(p2, p3));
        float d2 = fmaxf(fmaf(me.x, me.x, me.y * me.y) + ms, 0.f);
        s_row[tid] = make_float4(me.x, me.y, sqrtf(d2), 0.f);
    }
    __syncthreads();

    int rsub = tid >> 6;
    #pragma unroll
    for (int c = 0; c < 4; c++) {
        if (c >= 2) {                         // recycle buffer (c-2)'s group
            if (tid == 0)
                asm volatile("cp.async.bulk.wait_group 1;" ::: "memory");
            __syncthreads();
        }
        float* buf   = (float*)(dynbuf + (size_t)(c & 1) * 65536);
        int    rbase = c << 6;                // 64 rows per chunk
        #pragma unroll 16
        for (int r0 = 0; r0 < 64; r0 += 4) {
            int lr = r0 + rsub;
            float4 rw = s_row[rbase + lr];
            float4 v;
            v.x = fmaf(rw.x, A0.x, fmaf(rw.y, A1.x, fmaf(rw.z, C.x, Dv.x)));
            v.y = fmaf(rw.x, A0.y, fmaf(rw.y, A1.y, fmaf(rw.z, C.y, Dv.y)));
            v.z = fmaf(rw.x, A0.z, fmaf(rw.y, A1.z, fmaf(rw.z, C.z, Dv.z)));
            v.w = fmaf(rw.x, A0.w, fmaf(rw.y, A1.w, fmaf(rw.z, C.w, Dv.w)));
            *(float4*)(buf + (size_t)lr * EE + e0) = v;
        }
        __syncthreads();
        if (tid == 0) {
            asm volatile("fence.proxy.async;" ::: "memory");
            float*   gdst  = out + (size_t)(row0 + rbase) * EE;
            unsigned saddr = smem_u32(buf);
            asm volatile(
                "cp.async.bulk.global.shared::cta.bulk_group [%0], [%1], %2;"
                :: "l"(gdst), "r"(saddr), "r"(65536u) : "memory");
            asm volatile("cp.async.bulk.commit_group;" ::: "memory");
        }
    }
    if (tid == 0)
        asm volatile("cp.async.bulk.wait_group 0;" ::: "memory");
}

// ---------------------------------------------------------------------------
extern "C" void kernel_launch(void* const* d_in, const int* in_sizes, int n_in,
                              void* d_out, int out_size)
{
    const float*    locs   = (const float*)d_in[0];
    const unsigned* probe  = (const unsigned*)d_in[1];
    const float*    W_node = (const float*)d_in[2];
    const float*    b_node = (const float*)d_in[3];
    const float*    W_dist = (const float*)d_in[4];
    const float*    b_dist = (const float*)d_in[5];
    const float*    W_out  = (const float*)d_in[6];
    const float*    b_out  = (const float*)d_in[7];
    float* out = (float*)d_out;

    cudaFuncSetAttribute(epi_kernel,
                         cudaFuncAttributeMaxDynamicSharedMemorySize, 131072);

    main1_kernel<<<144, 256>>>(locs, probe, W_node, b_node, W_dist, b_dist, W_out, b_out);
    epi_kernel<<<128, 256, 131072>>>(locs, out);
}